// round 3
// baseline (speedup 1.0000x reference)
#include <cuda_runtime.h>

// x: (B=16, L=8192, F=512) float32, contiguous.
// y[b,t,:] = x[b,t+1,:] - x[b,t,:]   for t < L-1
// y[b,L-1,:] = x[b,L-1,:] - x[b,L-2,:]
//
// Vectorized float4: F = 512 floats = 128 float4 per row, so each float4
// is fully inside one (b,t) row. Row stride in float4 units = 128.

static constexpr int F4_PER_ROW = 512 / 4;   // 128
static constexpr int L_STEPS    = 8192;

__global__ void __launch_bounds__(256)
diff1d_kernel(const float4* __restrict__ x, float4* __restrict__ y, int n4)
{
    int j = blockIdx.x * blockDim.x + threadIdx.x;
    if (j >= n4) return;

    int row = j >> 7;                  // j / F4_PER_ROW
    int t   = row & (L_STEPS - 1);     // L is power of two

    float4 a, b;
    if (t < L_STEPS - 1) {
        a = x[j];
        b = x[j + F4_PER_ROW];
    } else {
        a = x[j - F4_PER_ROW];
        b = x[j];
    }

    float4 r;
    r.x = b.x - a.x;
    r.y = b.y - a.y;
    r.z = b.z - a.z;
    r.w = b.w - a.w;
    y[j] = r;
}

extern "C" void kernel_launch(void* const* d_in, const int* in_sizes, int n_in,
                              void* d_out, int out_size)
{
    const float4* x = (const float4*)d_in[0];
    float4* y = (float4*)d_out;
    int n4 = out_size / 4;             // total float4 count = 16*8192*512/4

    int threads = 256;
    int blocks = (n4 + threads - 1) / threads;
    diff1d_kernel<<<blocks, threads>>>(x, y, n4);
}

// round 8
// speedup vs baseline: 1.0426x; 1.0426x over previous
#include <cuda_runtime.h>

// x: (B=16, L=8192, F=512) float32, contiguous.
// y[b,t,:] = x[b,t+1,:] - x[b,t,:]   for t < L-1
// y[b,L-1,:] = x[b,L-1,:] - x[b,L-2,:]
//
// float4-vectorized, ITEMS=4 per thread with front-batched loads (MLP_p1=8).
// Branchless edge handling: for t == L-1, y = x[t] - x[t-1] = -(x[t-1] - x[t]),
// so r = s * (x[jb] - x[j]) with jb = j +/- 128, s = +/-1.

static constexpr int F4_PER_ROW = 512 / 4;   // 128
static constexpr int L_STEPS    = 8192;
static constexpr int ITEMS      = 4;
static constexpr int THREADS    = 256;

__global__ void __launch_bounds__(THREADS)
diff1d_kernel(const float4* __restrict__ x, float4* __restrict__ y, int n4)
{
    int base = blockIdx.x * (THREADS * ITEMS) + threadIdx.x;

    int   jj[ITEMS];
    float ss[ITEMS];
    float4 a[ITEMS];
    float4 b[ITEMS];

    // Index math + front-batched loads (8 independent LDG.128)
    #pragma unroll
    for (int i = 0; i < ITEMS; i++) {
        int j   = base + i * THREADS;
        int t   = (j >> 7) & (L_STEPS - 1);
        bool last = (t == L_STEPS - 1);
        int jb  = j + (last ? -F4_PER_ROW : F4_PER_ROW);
        jj[i]   = j;
        ss[i]   = last ? -1.0f : 1.0f;
        a[i]    = x[j];
        b[i]    = x[jb];
    }

    #pragma unroll
    for (int i = 0; i < ITEMS; i++) {
        float4 r;
        r.x = ss[i] * (b[i].x - a[i].x);
        r.y = ss[i] * (b[i].y - a[i].y);
        r.z = ss[i] * (b[i].z - a[i].z);
        r.w = ss[i] * (b[i].w - a[i].w);
        y[jj[i]] = r;
    }
}

extern "C" void kernel_launch(void* const* d_in, const int* in_sizes, int n_in,
                              void* d_out, int out_size)
{
    const float4* x = (const float4*)d_in[0];
    float4* y = (float4*)d_out;
    int n4 = out_size / 4;             // 16*8192*512/4 = 16,777,216

    int tile = THREADS * ITEMS;        // 1024 float4 per block
    int blocks = (n4 + tile - 1) / tile;   // 16384, exact division
    diff1d_kernel<<<blocks, THREADS>>>(x, y, n4);
}